// round 5
// baseline (speedup 1.0000x reference)
#include <cuda_runtime.h>
#include <math.h>

#define NATOM 2048
#define NTOK  512
#define CDIM  128
#define CZD   16
#define NHEADS 4
#define CHD   32
#define NBL   3
#define NHID  256
#define NQ    32
#define NKEY  128
#define NQB   (NATOM/NQ)
#define EPS   1e-5f
#define NEGBIG -1e30f
#define NC    (NATOM*CDIM)

// ---------------- scratch ----------------
__device__ float g_maskbias[NATOM];
__device__ float g_lns[NC];
__device__ float g_gate1[NBL*NC];
__device__ float g_shift1[NBL*NC];
__device__ float g_gate2[NBL*NC];
__device__ float g_shift2[NBL*NC];
__device__ float g_og1[NBL*NC];
__device__ float g_og2[NBL*NC];
__device__ float g_pb[NBL*NHEADS*NATOM*NKEY];
__device__ float g_a[NC];
__device__ float g_an[NC];
__device__ float g_q[NC];
__device__ float g_k[NC];
__device__ float g_v[NC];
__device__ float g_g[NC];
__device__ float g_ob[NC];

__device__ __forceinline__ float sigm(float x){ return 1.f/(1.f+expf(-x)); }

// packed fp32x2 helpers (FFMA2)
__device__ __forceinline__ unsigned long long pk2(float x, float y){
    unsigned long long r;
    asm("mov.b64 %0, {%1, %2};" : "=l"(r) : "f"(x), "f"(y));
    return r;
}
__device__ __forceinline__ void upk2(unsigned long long v, float &x, float &y){
    asm("mov.b64 {%0, %1}, %2;" : "=f"(x), "=f"(y) : "l"(v));
}
__device__ __forceinline__ void ffma2(unsigned long long &d, unsigned long long a, unsigned long long b){
    asm("fma.rn.f32x2 %0, %1, %2, %0;" : "+l"(d) : "l"(a), "l"(b));
}

// ---------------- copy in/out ----------------
__global__ void copy_in_kernel(const float* __restrict__ src){
    int i = blockIdx.x*256 + threadIdx.x;
    g_a[i] = src[i];
}
__global__ void copy_out_kernel(float* __restrict__ dst){
    int i = blockIdx.x*256 + threadIdx.x;
    dst[i] = g_a[i];
}

// ---------------- mask bias ----------------
__global__ void maskbias_kernel(const float* __restrict__ a2t, const float* __restrict__ tm){
    int w = threadIdx.x >> 5, l = threadIdx.x & 31;
    int n = blockIdx.x*8 + w;
    const float* row = a2t + (size_t)n*NTOK;
    float s = 0.f;
    for (int i = l; i < NTOK; i += 32) s += row[i]*tm[i];
    #pragma unroll
    for (int o = 16; o; o >>= 1) s += __shfl_xor_sync(0xffffffffu, s, o);
    if (l == 0) g_maskbias[n] = (s - 1.0f)*1e9f;
}

// ---------------- LN(cl) ----------------
__global__ void ln_cl_kernel(const float* __restrict__ in){
    int w = threadIdx.x >> 5, l = threadIdx.x & 31;
    int base = blockIdx.x*16 + w*4;
    for (int r = 0; r < 4; r++){
        const float* row = in + (size_t)(base+r)*CDIM;
        float x0=row[l], x1=row[l+32], x2=row[l+64], x3=row[l+96];
        float s = x0+x1+x2+x3;
        float s2 = x0*x0+x1*x1+x2*x2+x3*x3;
        #pragma unroll
        for (int o = 16; o; o >>= 1){
            s  += __shfl_xor_sync(0xffffffffu, s, o);
            s2 += __shfl_xor_sync(0xffffffffu, s2, o);
        }
        float mean = s*(1.f/CDIM);
        float var  = s2*(1.f/CDIM) - mean*mean;
        float rstd = rsqrtf(var + EPS);
        float* orow = g_lns + (size_t)(base+r)*CDIM;
        orow[l]    = (x0-mean)*rstd;
        orow[l+32] = (x1-mean)*rstd;
        orow[l+64] = (x2-mean)*rstd;
        orow[l+96] = (x3-mean)*rstd;
    }
}

// ---------------- batched precompute: 18 GEMMs, FFMA2 inner loop ----------------
__global__ void pre_gemm_kernel(const float* __restrict__ lns, const float* __restrict__ cl,
    const float* __restrict__ a1gs, const float* __restrict__ a1ws,
    const float* __restrict__ a1bs, const float* __restrict__ a1wsb,
    const float* __restrict__ a2gs, const float* __restrict__ a2ws,
    const float* __restrict__ a2bs, const float* __restrict__ a2wsb,
    const float* __restrict__ wog1, const float* __restrict__ bog1,
    const float* __restrict__ wog2, const float* __restrict__ bog2)
{
    int my = blockIdx.y;
    int b = my/6, m = my%6;
    size_t oW = (size_t)b*CDIM*CDIM, o1 = (size_t)b*CDIM, oC = (size_t)b*NC;
    const float* in = lns; const float* gs = 0; const float* W = 0;
    const float* bias = 0; float* out = 0; int sig = 0;
    switch(m){
        case 0: gs=a1gs+o1; W=a1ws +oW; bias=a1bs+o1; sig=1; out=g_gate1 +oC; break;
        case 1: gs=a1gs+o1; W=a1wsb+oW;               sig=0; out=g_shift1+oC; break;
        case 2: gs=a2gs+o1; W=a2ws +oW; bias=a2bs+o1; sig=1; out=g_gate2 +oC; break;
        case 3: gs=a2gs+o1; W=a2wsb+oW;               sig=0; out=g_shift2+oC; break;
        case 4: in=cl; W=wog1+oW; bias=bog1+o1; sig=1; out=g_og1+oC; break;
        default: in=cl; W=wog2+oW; bias=bog2+o1; sig=1; out=g_og2+oC; break;
    }
    __shared__ __align__(16) float ins_t[CDIM][20];
    int t = threadIdx.x; int m0 = blockIdx.x*16;
    const float4* in4 = (const float4*)in;
    const float4* gs4 = (const float4*)gs;
    for (int idx = t; idx < 16*32; idx += 128){
        int r = idx >> 5, c4 = idx & 31;
        float4 v = in4[(size_t)(m0+r)*32 + c4];
        if (gs){ float4 g = gs4[c4]; v.x*=g.x; v.y*=g.y; v.z*=g.z; v.w*=g.w; }
        ins_t[c4*4+0][r] = v.x; ins_t[c4*4+1][r] = v.y;
        ins_t[c4*4+2][r] = v.z; ins_t[c4*4+3][r] = v.w;
    }
    __syncthreads();
    unsigned long long acc[8];
    #pragma unroll
    for (int i = 0; i < 8; i++) acc[i] = 0ull;
    #pragma unroll 4
    for (int k = 0; k < CDIM; k++){
        float w = W[k*CDIM + t];
        unsigned long long wp = pk2(w, w);
        const ulonglong2* row = (const ulonglong2*)ins_t[k];
        ulonglong2 a0 = row[0], a1 = row[1], a2 = row[2], a3 = row[3];
        ffma2(acc[0], a0.x, wp); ffma2(acc[1], a0.y, wp);
        ffma2(acc[2], a1.x, wp); ffma2(acc[3], a1.y, wp);
        ffma2(acc[4], a2.x, wp); ffma2(acc[5], a2.y, wp);
        ffma2(acc[6], a3.x, wp); ffma2(acc[7], a3.y, wp);
    }
    float bb = bias ? bias[t] : 0.f;
    #pragma unroll
    for (int i = 0; i < 8; i++){
        float v0, v1; upk2(acc[i], v0, v1);
        v0 += bb; v1 += bb;
        if (sig){ v0 = sigm(v0); v1 = sigm(v1); }
        out[(size_t)(m0+2*i  )*CDIM + t] = v0;
        out[(size_t)(m0+2*i+1)*CDIM + t] = v1;
    }
}

// ---------------- pair bias (mask + window folded) ----------------
__global__ void pb_kernel(const float* __restrict__ plm, const float* __restrict__ gz,
                          const float* __restrict__ bz, const float* __restrict__ wz){
    __shared__ float wzc[CZD][12];
    __shared__ float bzd[12];
    int t = threadIdx.x;
    if (t < CZD*12){
        int c = t/12, idx = t%12, b = idx>>2, h = idx&3;
        wzc[c][idx] = gz[b*CZD + c]*wz[(b*CZD + c)*4 + h];
    }
    if (t < 12){
        int b = t>>2, h = t&3; float s = 0.f;
        for (int c = 0; c < CZD; c++) s += bz[b*CZD + c]*wz[(b*CZD + c)*4 + h];
        bzd[t] = s;
    }
    __syncthreads();
    int gid = blockIdx.x*256 + t;
    int n = gid >> 7, slot = gid & 127;
    int m = (n & ~31) - 48 + slot;
    if (m < 0 || m >= NATOM){
        #pragma unroll
        for (int idx = 0; idx < 12; idx++)
            g_pb[((size_t)idx*NATOM + n)*NKEY + slot] = NEGBIG;
        return;
    }
    const float4* p = (const float4*)(plm + ((size_t)n*NATOM + m)*CZD);
    float x[16];
    float4 f;
    f = p[0]; x[0]=f.x; x[1]=f.y; x[2]=f.z; x[3]=f.w;
    f = p[1]; x[4]=f.x; x[5]=f.y; x[6]=f.z; x[7]=f.w;
    f = p[2]; x[8]=f.x; x[9]=f.y; x[10]=f.z; x[11]=f.w;
    f = p[3]; x[12]=f.x; x[13]=f.y; x[14]=f.z; x[15]=f.w;
    float s = 0.f, s2 = 0.f;
    #pragma unroll
    for (int c = 0; c < 16; c++){ s += x[c]; s2 += x[c]*x[c]; }
    float mean = s*(1.f/16.f);
    float var  = s2*(1.f/16.f) - mean*mean;
    float rstd = rsqrtf(var + EPS);
    float val[12];
    #pragma unroll
    for (int idx = 0; idx < 12; idx++) val[idx] = 0.f;
    #pragma unroll
    for (int c = 0; c < 16; c++){
        float z = (x[c]-mean)*rstd;
        #pragma unroll
        for (int idx = 0; idx < 12; idx++) val[idx] += z*wzc[c][idx];
    }
    float mb = g_maskbias[m];
    #pragma unroll
    for (int idx = 0; idx < 12; idx++)
        g_pb[((size_t)idx*NATOM + n)*NKEY + slot] = val[idx] + bzd[idx] + mb;
}

// ---------------- per-block: fused AdaLN + one of {q,k,v,g} projections, FFMA2 ------
__global__ void adaln_proj_kernel(const float* __restrict__ gate1, const float* __restrict__ shift1,
                                  const float* __restrict__ wq, const float* __restrict__ bq,
                                  const float* __restrict__ wk, const float* __restrict__ wv,
                                  const float* __restrict__ wg){
    __shared__ float als[16][CDIM];
    __shared__ __align__(16) float als_t[CDIM][20];
    int t = threadIdx.x; int m0 = blockIdx.x*16;
    int mat = blockIdx.y;
    int w = t >> 5, l = t & 31;
    for (int idx = t; idx < 16*CDIM; idx += 128){
        int r = idx >> 7, c = idx & 127;
        als[r][c] = g_a[(size_t)(m0+r)*CDIM + c];
    }
    __syncthreads();
    for (int r = 0; r < 4; r++){
        int i = w*4 + r; int n = m0 + i;
        float x0=als[i][l], x1=als[i][l+32], x2=als[i][l+64], x3=als[i][l+96];
        float s = x0+x1+x2+x3;
        float s2 = x0*x0+x1*x1+x2*x2+x3*x3;
        #pragma unroll
        for (int o = 16; o; o >>= 1){
            s  += __shfl_xor_sync(0xffffffffu, s, o);
            s2 += __shfl_xor_sync(0xffffffffu, s2, o);
        }
        float mean = s*(1.f/CDIM);
        float var  = s2*(1.f/CDIM) - mean*mean;
        float rstd = rsqrtf(var + EPS);
        float a0=(x0-mean)*rstd, a1=(x1-mean)*rstd, a2=(x2-mean)*rstd, a3=(x3-mean)*rstd;
        size_t nb = (size_t)n*CDIM;
        if (mat == 0){
            g_an[nb+l]=a0; g_an[nb+l+32]=a1; g_an[nb+l+64]=a2; g_an[nb+l+96]=a3;
        }
        als_t[l   ][i] = gate1[nb+l]   *a0 + shift1[nb+l];
        als_t[l+32][i] = gate1[nb+l+32]*a1 + shift1[nb+l+32];
        als_t[l+64][i] = gate1[nb+l+64]*a2 + shift1[nb+l+64];
        als_t[l+96][i] = gate1[nb+l+96]*a3 + shift1[nb+l+96];
    }
    __syncthreads();
    const float* W; float* O;
    switch(mat){
        case 0: W = wq; O = g_q; break;
        case 1: W = wk; O = g_k; break;
        case 2: W = wv; O = g_v; break;
        default: W = wg; O = g_g; break;
    }
    unsigned long long acc[8];
    #pragma unroll
    for (int i = 0; i < 8; i++) acc[i] = 0ull;
    #pragma unroll 4
    for (int k = 0; k < CDIM; k++){
        float wv_ = W[k*CDIM + t];
        unsigned long long wp = pk2(wv_, wv_);
        const ulonglong2* row = (const ulonglong2*)als_t[k];
        ulonglong2 a0 = row[0], a1 = row[1], a2 = row[2], a3 = row[3];
        ffma2(acc[0], a0.x, wp); ffma2(acc[1], a0.y, wp);
        ffma2(acc[2], a1.x, wp); ffma2(acc[3], a1.y, wp);
        ffma2(acc[4], a2.x, wp); ffma2(acc[5], a2.y, wp);
        ffma2(acc[6], a3.x, wp); ffma2(acc[7], a3.y, wp);
    }
    float bb = (mat == 0) ? bq[t] : 0.f;
    #pragma unroll
    for (int i = 0; i < 8; i++){
        float v0, v1; upk2(acc[i], v0, v1);
        v0 += bb; v1 += bb;
        if (mat == 3){ v0 = sigm(v0); v1 = sigm(v1); }
        O[(size_t)(m0+2*i  )*CDIM + t] = v0;
        O[(size_t)(m0+2*i+1)*CDIM + t] = v1;
    }
}

// ---------------- block-sparse attention ----------------
__global__ void attn_kernel(const float* __restrict__ pb){
    __shared__ __align__(16) float qs[32][32];
    __shared__ __align__(16) float vs[128][32];
    __shared__ __align__(16) float buf[128*32];
    int t = threadIdx.x;
    int j = blockIdx.x, h = blockIdx.y;
    int n0 = j*NQ, w0 = j*NQ - 48, hd0 = h*CHD;
    for (int idx = t; idx < 32*32; idx += 128){
        int i = idx >> 5, d = idx & 31;
        qs[i][d] = g_q[(size_t)(n0+i)*CDIM + hd0 + d];
    }
    for (int idx = t; idx < 128*32; idx += 128){
        int m = idx >> 5, d = idx & 31;
        int key = w0 + m;
        float kk = 0.f, vv = 0.f;
        if (key >= 0 && key < NATOM){
            kk = g_k[(size_t)key*CDIM + hd0 + d];
            vv = g_v[(size_t)key*CDIM + hd0 + d];
        }
        buf[m*32 + d] = kk; vs[m][d] = vv;
    }
    __syncthreads();
    // pack this thread's key vector into 16 fp32x2 pairs
    unsigned long long kp[16];
    #pragma unroll
    for (int d = 0; d < 16; d++){
        kp[d] = pk2(buf[t*32 + 2*d], buf[t*32 + 2*d + 1]);
    }
    __syncthreads();
    const float scale = 0.17677669529663687f;
    const float* pbr = pb + (size_t)h*NATOM*NKEY + (size_t)n0*NKEY;
    #pragma unroll 4
    for (int i = 0; i < 32; i++){
        unsigned long long acc0 = 0ull, acc1 = 0ull;
        const ulonglong2* qrow = (const ulonglong2*)qs[i];
        #pragma unroll
        for (int p = 0; p < 8; p++){          // 8 x ulonglong2 = 32 floats
            ulonglong2 q = qrow[p];
            ffma2(acc0, q.x, kp[2*p  ]);      // pair 2p   <-> dims (4p,4p+1)... matched pairs
            ffma2(acc1, q.y, kp[2*p+1]);      // pair 2p+1 <-> dims (4p+2,4p+3)
        }
        float s0,s1,s2,s3;
        upk2(acc0, s0, s1); upk2(acc1, s2, s3);
        buf[i*128 + t] = (s0+s1+s2+s3)*scale + pbr[i*NKEY + t];
    }
    __syncthreads();
    int w = t >> 5, l = t & 31;
    for (int r = 0; r < 8; r++){
        int i = w*8 + r;
        float x0=buf[i*128+l], x1=buf[i*128+l+32], x2=buf[i*128+l+64], x3=buf[i*128+l+96];
        float mx = fmaxf(fmaxf(x0,x1), fmaxf(x2,x3));
        #pragma unroll
        for (int o = 16; o; o >>= 1) mx = fmaxf(mx, __shfl_xor_sync(0xffffffffu, mx, o));
        float e0=expf(x0-mx), e1=expf(x1-mx), e2=expf(x2-mx), e3=expf(x3-mx);
        float s = e0+e1+e2+e3;
        #pragma unroll
        for (int o = 16; o; o >>= 1) s += __shfl_xor_sync(0xffffffffu, s, o);
        float inv = 1.f/s;
        buf[i*128+l]=e0*inv; buf[i*128+l+32]=e1*inv; buf[i*128+l+64]=e2*inv; buf[i*128+l+96]=e3*inv;
    }
    __syncthreads();
    int i = t >> 2, d0 = (t & 3)*8;
    unsigned long long acc[4];
    #pragma unroll
    for (int dd = 0; dd < 4; dd++) acc[dd] = 0ull;
    #pragma unroll 4
    for (int kk = 0; kk < 128; kk++){
        float wgt = buf[i*128 + kk];
        unsigned long long wp = pk2(wgt, wgt);
        ulonglong2 v01 = *(const ulonglong2*)&vs[kk][d0];
        ffma2(acc[0], v01.x, wp); ffma2(acc[1], v01.y, wp);
        ulonglong2 v23 = *(const ulonglong2*)&vs[kk][d0+4];
        ffma2(acc[2], v23.x, wp); ffma2(acc[3], v23.y, wp);
    }
    int n = n0 + i;
    #pragma unroll
    for (int dd = 0; dd < 4; dd++){
        float v0, v1; upk2(acc[dd], v0, v1);
        int c = hd0 + d0 + 2*dd;
        g_ob[(size_t)n*CDIM + c]     = g_g[(size_t)n*CDIM + c]    *v0;
        g_ob[(size_t)n*CDIM + c + 1] = g_g[(size_t)n*CDIM + c + 1]*v1;
    }
}

// ---------------- fused tail: outproj*og1 + SwiGLU transition + residual ----------
__global__ void tail_kernel(const float* __restrict__ wo, const float* __restrict__ og1,
                            const float* __restrict__ gate2, const float* __restrict__ shift2,
                            const float* __restrict__ wt1, const float* __restrict__ wt2,
                            const float* __restrict__ wt3, const float* __restrict__ og2){
    __shared__ __align__(16) float obs_t[CDIM][12];
    __shared__ __align__(16) float a2s_t[CDIM][12];
    __shared__ __align__(16) float hid_t[NHID][12];
    int t = threadIdx.x;               // 256
    int m0 = blockIdx.x*8;
    for (int idx = t; idx < 8*CDIM; idx += 256){
        int r = idx >> 7, c = idx & 127;
        size_t o = (size_t)(m0+r)*CDIM + c;
        obs_t[c][r] = g_ob[o];
        a2s_t[c][r] = gate2[o]*g_an[o] + shift2[o];
    }
    __syncthreads();
    int col = t & 127, half = t >> 7;
    int r0 = half*4;
    float attr[4];
    // phase A: outproj
    {
        unsigned long long acc[2] = {0ull, 0ull};
        #pragma unroll 4
        for (int k = 0; k < CDIM; k++){
            float w = wo[k*CDIM + col];
            unsigned long long wp = pk2(w, w);
            ulonglong2 a = *(const ulonglong2*)&obs_t[k][r0];
            ffma2(acc[0], a.x, wp); ffma2(acc[1], a.y, wp);
        }
        float v0,v1,v2,v3;
        upk2(acc[0], v0, v1); upk2(acc[1], v2, v3);
        size_t ob = (size_t)(m0+r0)*CDIM + col;
        attr[0] = og1[ob         ]*v0;
        attr[1] = og1[ob +   CDIM]*v1;
        attr[2] = og1[ob + 2*CDIM]*v2;
        attr[3] = og1[ob + 3*CDIM]*v3;
    }
    // phase B: trans1 -> hidden
    {
        unsigned long long acc1[4], acc2[4];
        #pragma unroll
        for (int i = 0; i < 4; i++){ acc1[i]=0ull; acc2[i]=0ull; }
        #pragma unroll 4
        for (int k = 0; k < CDIM; k++){
            float w1 = wt1[k*NHID + t], w2 = wt2[k*NHID + t];
            unsigned long long wp1 = pk2(w1, w1), wp2 = pk2(w2, w2);
            const ulonglong2* row = (const ulonglong2*)a2s_t[k];
            ulonglong2 a01 = row[0], a23 = row[1];
            ffma2(acc1[0], a01.x, wp1); ffma2(acc1[1], a01.y, wp1);
            ffma2(acc1[2], a23.x, wp1); ffma2(acc1[3], a23.y, wp1);
            ffma2(acc2[0], a01.x, wp2); ffma2(acc2[1], a01.y, wp2);
            ffma2(acc2[2], a23.x, wp2); ffma2(acc2[3], a23.y, wp2);
        }
        #pragma unroll
        for (int i = 0; i < 4; i++){
            float h1a, h1b, h2a, h2b;
            upk2(acc1[i], h1a, h1b); upk2(acc2[i], h2a, h2b);
            hid_t[t][2*i  ] = h1a*sigm(h1a)*h2a;
            hid_t[t][2*i+1] = h1b*sigm(h1b)*h2b;
        }
    }
    __syncthreads();
    // phase C: trans2 + og2 gate + residual
    {
        unsigned long long acc[2] = {0ull, 0ull};
        #pragma unroll 4
        for (int k = 0; k < NHID; k++){
            float w = wt3[k*CDIM + col];
            unsigned long long wp = pk2(w, w);
            ulonglong2 a = *(const ulonglong2*)&hid_t[k][r0];
            ffma2(acc[0], a.x, wp); ffma2(acc[1], a.y, wp);
        }
        float v0,v1,v2,v3;
        upk2(acc[0], v0, v1); upk2(acc[1], v2, v3);
        size_t ob = (size_t)(m0+r0)*CDIM + col;
        g_a[ob         ] = attr[0] + og2[ob         ]*v0;
        g_a[ob +   CDIM] = attr[1] + og2[ob +   CDIM]*v1;
        g_a[ob + 2*CDIM] = attr[2] + og2[ob + 2*CDIM]*v2;
        g_a[ob + 3*CDIM] = attr[3] + og2[ob + 3*CDIM]*v3;
    }
}

// ---------------- host launcher ----------------
extern "C" void kernel_launch(void* const* d_in, const int* in_sizes, int n_in,
                              void* d_out, int out_size){
    const float* ql       = (const float*)d_in[0];
    const float* cl       = (const float*)d_in[1];
    const float* plm      = (const float*)d_in[2];
    const float* a2t      = (const float*)d_in[3];
    const float* tm       = (const float*)d_in[4];
    const float* ada1_gs  = (const float*)d_in[5];
    const float* ada1_ws  = (const float*)d_in[6];
    const float* ada1_bs  = (const float*)d_in[7];
    const float* ada1_wsb = (const float*)d_in[8];
    const float* wq       = (const float*)d_in[9];
    const float* bq       = (const float*)d_in[10];
    const float* wk       = (const float*)d_in[11];
    const float* wv       = (const float*)d_in[12];
    const float* gz       = (const float*)d_in[13];
    const float* bz       = (const float*)d_in[14];
    const float* wz       = (const float*)d_in[15];
    const float* wg       = (const float*)d_in[16];
    const float* wo       = (const float*)d_in[17];
    const float* wog1     = (const float*)d_in[18];
    const float* bog1     = (const float*)d_in[19];
    const float* ada2_gs  = (const float*)d_in[20];
    const float* ada2_ws  = (const float*)d_in[21];
    const float* ada2_bs  = (const float*)d_in[22];
    const float* ada2_wsb = (const float*)d_in[23];
    const float* wt1      = (const float*)d_in[24];
    const float* wt2      = (const float*)d_in[25];
    const float* wt3      = (const float*)d_in[26];
    const float* wog2     = (const float*)d_in[27];
    const float* bog2     = (const float*)d_in[28];

    float *p_lns, *p_gate1, *p_shift1, *p_gate2, *p_shift2, *p_og1, *p_og2, *p_pb;
    cudaGetSymbolAddress((void**)&p_lns,    g_lns);
    cudaGetSymbolAddress((void**)&p_gate1,  g_gate1);
    cudaGetSymbolAddress((void**)&p_shift1, g_shift1);
    cudaGetSymbolAddress((void**)&p_gate2,  g_gate2);
    cudaGetSymbolAddress((void**)&p_shift2, g_shift2);
    cudaGetSymbolAddress((void**)&p_og1,    g_og1);
    cudaGetSymbolAddress((void**)&p_og2,    g_og2);
    cudaGetSymbolAddress((void**)&p_pb,     g_pb);

    copy_in_kernel<<<NC/256, 256>>>(ql);
    ln_cl_kernel<<<NATOM/16, 128>>>(cl);
    maskbias_kernel<<<NATOM/8, 256>>>(a2t, tm);

    dim3 pg(NATOM/16, 18);
    pre_gemm_kernel<<<pg, 128>>>(p_lns, cl,
        ada1_gs, ada1_ws, ada1_bs, ada1_wsb,
        ada2_gs, ada2_ws, ada2_bs, ada2_wsb,
        wog1, bog1, wog2, bog2);

    pb_kernel<<<NATOM*NKEY/256, 256>>>(plm, gz, bz, wz);

    for (int b = 0; b < NBL; b++){
        size_t oC = (size_t)b*NC, oW = (size_t)b*CDIM*CDIM;
        dim3 qg(NATOM/16, 4);
        adaln_proj_kernel<<<qg, 128>>>(p_gate1+oC, p_shift1+oC,
                                       wq+oW, bq+(size_t)b*CDIM, wk+oW, wv+oW, wg+oW);
        dim3 ag(NQB, NHEADS);
        attn_kernel<<<ag, 128>>>(p_pb + (size_t)b*NHEADS*NATOM*NKEY);
        tail_kernel<<<NATOM/8, 256>>>(wo+oW, p_og1+oC, p_gate2+oC, p_shift2+oC,
                                      wt1+(size_t)b*CDIM*NHID, wt2+(size_t)b*CDIM*NHID,
                                      wt3+(size_t)b*NHID*CDIM, p_og2+oC);
    }
    copy_out_kernel<<<NC/256, 256>>>((float*)d_out);
}

// round 7
// speedup vs baseline: 1.1559x; 1.1559x over previous
#include <cuda_runtime.h>
#include <math.h>

#define NATOM 2048
#define NTOK  512
#define CDIM  128
#define CZD   16
#define NHEADS 4
#define CHD   32
#define NBL   3
#define NHID  256
#define NQ    32
#define NKEY  128
#define NQB   (NATOM/NQ)
#define EPS   1e-5f
#define NEGBIG -1e30f
#define NC    (NATOM*CDIM)

// ---------------- scratch ----------------
__device__ float g_maskbias[NATOM];
__device__ float g_lns[NC];
__device__ float g_gate1[NBL*NC];
__device__ float g_shift1[NBL*NC];
__device__ float g_gate2[NBL*NC];
__device__ float g_shift2[NBL*NC];
__device__ float g_og1[NBL*NC];
__device__ float g_og2[NBL*NC];
__device__ float g_pb[NBL*NHEADS*NATOM*NKEY];
__device__ float g_a[NC];
__device__ float g_an[NC];
__device__ float g_q[NC];
__device__ float g_k[NC];
__device__ float g_v[NC];
__device__ float g_g[NC];
__device__ float g_ob[NC];

__device__ __forceinline__ float sigm(float x){ return 1.f/(1.f+expf(-x)); }

// ---------------- copy in/out ----------------
__global__ void copy_in_kernel(const float* __restrict__ src){
    int i = blockIdx.x*256 + threadIdx.x;
    g_a[i] = src[i];
}
__global__ void copy_out_kernel(float* __restrict__ dst){
    int i = blockIdx.x*256 + threadIdx.x;
    dst[i] = g_a[i];
}

// ---------------- mask bias ----------------
__global__ void maskbias_kernel(const float* __restrict__ a2t, const float* __restrict__ tm){
    int w = threadIdx.x >> 5, l = threadIdx.x & 31;
    int n = blockIdx.x*8 + w;
    const float* row = a2t + (size_t)n*NTOK;
    float s = 0.f;
    for (int i = l; i < NTOK; i += 32) s += row[i]*tm[i];
    #pragma unroll
    for (int o = 16; o; o >>= 1) s += __shfl_xor_sync(0xffffffffu, s, o);
    if (l == 0) g_maskbias[n] = (s - 1.0f)*1e9f;
}

// ---------------- LN(cl) ----------------
__global__ void ln_cl_kernel(const float* __restrict__ in){
    int w = threadIdx.x >> 5, l = threadIdx.x & 31;
    int base = blockIdx.x*16 + w*4;
    for (int r = 0; r < 4; r++){
        const float* row = in + (size_t)(base+r)*CDIM;
        float x0=row[l], x1=row[l+32], x2=row[l+64], x3=row[l+96];
        float s = x0+x1+x2+x3;
        float s2 = x0*x0+x1*x1+x2*x2+x3*x3;
        #pragma unroll
        for (int o = 16; o; o >>= 1){
            s  += __shfl_xor_sync(0xffffffffu, s, o);
            s2 += __shfl_xor_sync(0xffffffffu, s2, o);
        }
        float mean = s*(1.f/CDIM);
        float var  = s2*(1.f/CDIM) - mean*mean;
        float rstd = rsqrtf(var + EPS);
        float* orow = g_lns + (size_t)(base+r)*CDIM;
        orow[l]    = (x0-mean)*rstd;
        orow[l+32] = (x1-mean)*rstd;
        orow[l+64] = (x2-mean)*rstd;
        orow[l+96] = (x3-mean)*rstd;
    }
}

// ---------------- batched precompute: 18 GEMMs, 32-row tiles, 2 cols/thread --------
__global__ void pre_gemm_kernel(const float* __restrict__ lns, const float* __restrict__ cl,
    const float* __restrict__ a1gs, const float* __restrict__ a1ws,
    const float* __restrict__ a1bs, const float* __restrict__ a1wsb,
    const float* __restrict__ a2gs, const float* __restrict__ a2ws,
    const float* __restrict__ a2bs, const float* __restrict__ a2wsb,
    const float* __restrict__ wog1, const float* __restrict__ bog1,
    const float* __restrict__ wog2, const float* __restrict__ bog2)
{
    int my = blockIdx.y;
    int b = my/6, m = my%6;
    size_t oW = (size_t)b*CDIM*CDIM, o1 = (size_t)b*CDIM, oC = (size_t)b*NC;
    const float* in = lns; const float* gs = 0; const float* W = 0;
    const float* bias = 0; float* out = 0; int sig = 0;
    switch(m){
        case 0: gs=a1gs+o1; W=a1ws +oW; bias=a1bs+o1; sig=1; out=g_gate1 +oC; break;
        case 1: gs=a1gs+o1; W=a1wsb+oW;               sig=0; out=g_shift1+oC; break;
        case 2: gs=a2gs+o1; W=a2ws +oW; bias=a2bs+o1; sig=1; out=g_gate2 +oC; break;
        case 3: gs=a2gs+o1; W=a2wsb+oW;               sig=0; out=g_shift2+oC; break;
        case 4: in=cl; W=wog1+oW; bias=bog1+o1; sig=1; out=g_og1+oC; break;
        default: in=cl; W=wog2+oW; bias=bog2+o1; sig=1; out=g_og2+oC; break;
    }
    __shared__ __align__(16) float ins[32][CDIM];
    int t = threadIdx.x; int m0 = blockIdx.x*32;
    const float4* in4 = (const float4*)in;
    const float4* gs4 = (const float4*)gs;
    for (int idx = t; idx < 32*32; idx += 128){
        int r = idx >> 5, c4 = idx & 31;
        float4 v = in4[(size_t)(m0+r)*32 + c4];
        if (gs){ float4 g = gs4[c4]; v.x*=g.x; v.y*=g.y; v.z*=g.z; v.w*=g.w; }
        *(float4*)&ins[r][c4*4] = v;
    }
    __syncthreads();
    int c0 = (t & 63)*2;           // even column
    int rg = (t >> 6)*16;          // row group: 0 or 16
    float acc0[16], acc1[16];
    #pragma unroll
    for (int i = 0; i < 16; i++){ acc0[i]=0.f; acc1[i]=0.f; }
    for (int k4 = 0; k4 < CDIM/4; k4++){
        float2 w0 = *(const float2*)&W[(k4*4+0)*CDIM + c0];
        float2 w1 = *(const float2*)&W[(k4*4+1)*CDIM + c0];
        float2 w2 = *(const float2*)&W[(k4*4+2)*CDIM + c0];
        float2 w3 = *(const float2*)&W[(k4*4+3)*CDIM + c0];
        #pragma unroll
        for (int i = 0; i < 16; i++){
            float4 a = *(const float4*)&ins[rg+i][k4*4];
            acc0[i] = fmaf(a.x, w0.x, fmaf(a.y, w1.x, fmaf(a.z, w2.x, fmaf(a.w, w3.x, acc0[i]))));
            acc1[i] = fmaf(a.x, w0.y, fmaf(a.y, w1.y, fmaf(a.z, w2.y, fmaf(a.w, w3.y, acc1[i]))));
        }
    }
    float b0 = bias ? bias[c0] : 0.f;
    float b1 = bias ? bias[c0+1] : 0.f;
    #pragma unroll
    for (int i = 0; i < 16; i++){
        float v0 = acc0[i] + b0, v1 = acc1[i] + b1;
        if (sig){ v0 = sigm(v0); v1 = sigm(v1); }
        float* o = out + (size_t)(m0+rg+i)*CDIM + c0;
        o[0] = v0; o[1] = v1;
    }
}

// ---------------- pair bias (mask + window folded) ----------------
__global__ void pb_kernel(const float* __restrict__ plm, const float* __restrict__ gz,
                          const float* __restrict__ bz, const float* __restrict__ wz){
    __shared__ float wzc[CZD][12];
    __shared__ float bzd[12];
    int t = threadIdx.x;
    if (t < CZD*12){
        int c = t/12, idx = t%12, b = idx>>2, h = idx&3;
        wzc[c][idx] = gz[b*CZD + c]*wz[(b*CZD + c)*4 + h];
    }
    if (t < 12){
        int b = t>>2, h = t&3; float s = 0.f;
        for (int c = 0; c < CZD; c++) s += bz[b*CZD + c]*wz[(b*CZD + c)*4 + h];
        bzd[t] = s;
    }
    __syncthreads();
    int gid = blockIdx.x*256 + t;
    int n = gid >> 7, slot = gid & 127;
    int m = (n & ~31) - 48 + slot;
    if (m < 0 || m >= NATOM){
        #pragma unroll
        for (int idx = 0; idx < 12; idx++)
            g_pb[((size_t)idx*NATOM + n)*NKEY + slot] = NEGBIG;
        return;
    }
    const float4* p = (const float4*)(plm + ((size_t)n*NATOM + m)*CZD);
    float x[16];
    float4 f;
    f = p[0]; x[0]=f.x; x[1]=f.y; x[2]=f.z; x[3]=f.w;
    f = p[1]; x[4]=f.x; x[5]=f.y; x[6]=f.z; x[7]=f.w;
    f = p[2]; x[8]=f.x; x[9]=f.y; x[10]=f.z; x[11]=f.w;
    f = p[3]; x[12]=f.x; x[13]=f.y; x[14]=f.z; x[15]=f.w;
    float s = 0.f, s2 = 0.f;
    #pragma unroll
    for (int c = 0; c < 16; c++){ s += x[c]; s2 += x[c]*x[c]; }
    float mean = s*(1.f/16.f);
    float var  = s2*(1.f/16.f) - mean*mean;
    float rstd = rsqrtf(var + EPS);
    float val[12];
    #pragma unroll
    for (int idx = 0; idx < 12; idx++) val[idx] = 0.f;
    #pragma unroll
    for (int c = 0; c < 16; c++){
        float z = (x[c]-mean)*rstd;
        #pragma unroll
        for (int idx = 0; idx < 12; idx++) val[idx] += z*wzc[c][idx];
    }
    float mb = g_maskbias[m];
    #pragma unroll
    for (int idx = 0; idx < 12; idx++)
        g_pb[((size_t)idx*NATOM + n)*NKEY + slot] = val[idx] + bzd[idx] + mb;
}

// ---------------- per-block: fused AdaLN + one of {q,k,v,g}, 32-row tiles ----------
__global__ void adaln_proj_kernel(const float* __restrict__ gate1, const float* __restrict__ shift1,
                                  const float* __restrict__ wq, const float* __restrict__ bq,
                                  const float* __restrict__ wk, const float* __restrict__ wv,
                                  const float* __restrict__ wg){
    __shared__ __align__(16) float als[32][CDIM];
    int t = threadIdx.x; int m0 = blockIdx.x*32;
    int mat = blockIdx.y;
    int w = t >> 5, l = t & 31;
    for (int idx = t; idx < 32*32; idx += 128){
        int r = idx >> 5, c4 = idx & 31;
        *(float4*)&als[r][c4*4] = *(const float4*)(g_a + (size_t)(m0+r)*CDIM + c4*4);
    }
    __syncthreads();
    for (int r = 0; r < 8; r++){
        int i = w*8 + r; int n = m0 + i;
        float x0=als[i][l], x1=als[i][l+32], x2=als[i][l+64], x3=als[i][l+96];
        float s = x0+x1+x2+x3;
        float s2 = x0*x0+x1*x1+x2*x2+x3*x3;
        #pragma unroll
        for (int o = 16; o; o >>= 1){
            s  += __shfl_xor_sync(0xffffffffu, s, o);
            s2 += __shfl_xor_sync(0xffffffffu, s2, o);
        }
        float mean = s*(1.f/CDIM);
        float var  = s2*(1.f/CDIM) - mean*mean;
        float rstd = rsqrtf(var + EPS);
        float a0=(x0-mean)*rstd, a1=(x1-mean)*rstd, a2=(x2-mean)*rstd, a3=(x3-mean)*rstd;
        size_t nb = (size_t)n*CDIM;
        if (mat == 0){
            g_an[nb+l]=a0; g_an[nb+l+32]=a1; g_an[nb+l+64]=a2; g_an[nb+l+96]=a3;
        }
        als[i][l]    = gate1[nb+l]   *a0 + shift1[nb+l];
        als[i][l+32] = gate1[nb+l+32]*a1 + shift1[nb+l+32];
        als[i][l+64] = gate1[nb+l+64]*a2 + shift1[nb+l+64];
        als[i][l+96] = gate1[nb+l+96]*a3 + shift1[nb+l+96];
    }
    __syncthreads();
    const float* W; float* O;
    switch(mat){
        case 0: W = wq; O = g_q; break;
        case 1: W = wk; O = g_k; break;
        case 2: W = wv; O = g_v; break;
        default: W = wg; O = g_g; break;
    }
    int c0 = (t & 63)*2;
    int rg = (t >> 6)*16;
    float acc0[16], acc1[16];
    #pragma unroll
    for (int i = 0; i < 16; i++){ acc0[i]=0.f; acc1[i]=0.f; }
    for (int k4 = 0; k4 < CDIM/4; k4++){
        float2 w0 = *(const float2*)&W[(k4*4+0)*CDIM + c0];
        float2 w1 = *(const float2*)&W[(k4*4+1)*CDIM + c0];
        float2 w2 = *(const float2*)&W[(k4*4+2)*CDIM + c0];
        float2 w3 = *(const float2*)&W[(k4*4+3)*CDIM + c0];
        #pragma unroll
        for (int i = 0; i < 16; i++){
            float4 a = *(const float4*)&als[rg+i][k4*4];
            acc0[i] = fmaf(a.x, w0.x, fmaf(a.y, w1.x, fmaf(a.z, w2.x, fmaf(a.w, w3.x, acc0[i]))));
            acc1[i] = fmaf(a.x, w0.y, fmaf(a.y, w1.y, fmaf(a.z, w2.y, fmaf(a.w, w3.y, acc1[i]))));
        }
    }
    float b0 = (mat == 0) ? bq[c0] : 0.f;
    float b1 = (mat == 0) ? bq[c0+1] : 0.f;
    #pragma unroll
    for (int i = 0; i < 16; i++){
        float v0 = acc0[i] + b0, v1 = acc1[i] + b1;
        if (mat == 3){ v0 = sigm(v0); v1 = sigm(v1); }
        float* o = O + (size_t)(m0+rg+i)*CDIM + c0;
        o[0] = v0; o[1] = v1;
    }
}

// ---------------- block-sparse attention (R3 proven version) ----------------
__global__ void attn_kernel(const float* __restrict__ pb){
    __shared__ __align__(16) float qs[32][32];
    __shared__ __align__(16) float vs[128][32];
    __shared__ __align__(16) float buf[128*32];
    int t = threadIdx.x;
    int j = blockIdx.x, h = blockIdx.y;
    int n0 = j*NQ, w0 = j*NQ - 48, hd0 = h*CHD;
    for (int idx = t; idx < 32*32; idx += 128){
        int i = idx >> 5, d = idx & 31;
        qs[i][d] = g_q[(size_t)(n0+i)*CDIM + hd0 + d];
    }
    for (int idx = t; idx < 128*32; idx += 128){
        int m = idx >> 5, d = idx & 31;
        int key = w0 + m;
        float kk = 0.f, vv = 0.f;
        if (key >= 0 && key < NATOM){
            kk = g_k[(size_t)key*CDIM + hd0 + d];
            vv = g_v[(size_t)key*CDIM + hd0 + d];
        }
        buf[m*32 + d] = kk; vs[m][d] = vv;
    }
    __syncthreads();
    float kr[32];
    #pragma unroll
    for (int d = 0; d < 32; d++) kr[d] = buf[t*32 + d];
    __syncthreads();
    const float scale = 0.17677669529663687f;
    const float* pbr = pb + (size_t)h*NATOM*NKEY + (size_t)n0*NKEY;
    #pragma unroll 4
    for (int i = 0; i < 32; i++){
        float acc = 0.f;
        #pragma unroll
        for (int d4 = 0; d4 < 8; d4++){
            float4 q = *(const float4*)&qs[i][d4*4];
            acc = fmaf(q.x, kr[d4*4+0], fmaf(q.y, kr[d4*4+1],
                  fmaf(q.z, kr[d4*4+2], fmaf(q.w, kr[d4*4+3], acc))));
        }
        buf[i*128 + t] = acc*scale + pbr[i*NKEY + t];
    }
    __syncthreads();
    int w = t >> 5, l = t & 31;
    for (int r = 0; r < 8; r++){
        int i = w*8 + r;
        float x0=buf[i*128+l], x1=buf[i*128+l+32], x2=buf[i*128+l+64], x3=buf[i*128+l+96];
        float mx = fmaxf(fmaxf(x0,x1), fmaxf(x2,x3));
        #pragma unroll
        for (int o = 16; o; o >>= 1) mx = fmaxf(mx, __shfl_xor_sync(0xffffffffu, mx, o));
        float e0=expf(x0-mx), e1=expf(x1-mx), e2=expf(x2-mx), e3=expf(x3-mx);
        float s = e0+e1+e2+e3;
        #pragma unroll
        for (int o = 16; o; o >>= 1) s += __shfl_xor_sync(0xffffffffu, s, o);
        float inv = 1.f/s;
        buf[i*128+l]=e0*inv; buf[i*128+l+32]=e1*inv; buf[i*128+l+64]=e2*inv; buf[i*128+l+96]=e3*inv;
    }
    __syncthreads();
    int i = t >> 2, d0 = (t & 3)*8;
    float acc[8];
    #pragma unroll
    for (int dd = 0; dd < 8; dd++) acc[dd] = 0.f;
    #pragma unroll 4
    for (int kk = 0; kk < 128; kk++){
        float wgt = buf[i*128 + kk];
        float4 v0 = *(const float4*)&vs[kk][d0];
        float4 v1 = *(const float4*)&vs[kk][d0+4];
        acc[0] = fmaf(wgt, v0.x, acc[0]); acc[1] = fmaf(wgt, v0.y, acc[1]);
        acc[2] = fmaf(wgt, v0.z, acc[2]); acc[3] = fmaf(wgt, v0.w, acc[3]);
        acc[4] = fmaf(wgt, v1.x, acc[4]); acc[5] = fmaf(wgt, v1.y, acc[5]);
        acc[6] = fmaf(wgt, v1.z, acc[6]); acc[7] = fmaf(wgt, v1.w, acc[7]);
    }
    int n = n0 + i;
    #pragma unroll
    for (int dd = 0; dd < 8; dd++){
        int c = hd0 + d0 + dd;
        g_ob[(size_t)n*CDIM + c] = g_g[(size_t)n*CDIM + c]*acc[dd];
    }
}

// ---------------- fused tail: 16-row tiles, 2 cols/thread in A/C -------------------
__global__ void tail_kernel(const float* __restrict__ wo, const float* __restrict__ og1,
                            const float* __restrict__ gate2, const float* __restrict__ shift2,
                            const float* __restrict__ wt1, const float* __restrict__ wt2,
                            const float* __restrict__ wt3, const float* __restrict__ og2){
    __shared__ __align__(16) float obs[16][CDIM];
    __shared__ __align__(16) float a2s[16][CDIM];
    __shared__ __align__(16) float att[16][CDIM];
    __shared__ __align__(16) float hid[16][NHID];
    int t = threadIdx.x;               // 256
    int m0 = blockIdx.x*16;
    for (int idx = t; idx < 16*CDIM; idx += 256){
        int r = idx >> 7, c = idx & 127;
        size_t o = (size_t)(m0+r)*CDIM + c;
        obs[r][c] = g_ob[o];
        a2s[r][c] = gate2[o]*g_an[o] + shift2[o];
    }
    __syncthreads();
    // phase A: outproj — 2 cols x 4 rows per thread (64 col-pairs x 4 rowgroups)
    {
        int c0 = (t & 63)*2;
        int rg = (t >> 6)*4;
        float acc0[4] = {0,0,0,0}, acc1[4] = {0,0,0,0};
        for (int k4 = 0; k4 < CDIM/4; k4++){
            float2 w0 = *(const float2*)&wo[(k4*4+0)*CDIM + c0];
            float2 w1 = *(const float2*)&wo[(k4*4+1)*CDIM + c0];
            float2 w2 = *(const float2*)&wo[(k4*4+2)*CDIM + c0];
            float2 w3 = *(const float2*)&wo[(k4*4+3)*CDIM + c0];
            #pragma unroll
            for (int i = 0; i < 4; i++){
                float4 a = *(const float4*)&obs[rg+i][k4*4];
                acc0[i] = fmaf(a.x, w0.x, fmaf(a.y, w1.x, fmaf(a.z, w2.x, fmaf(a.w, w3.x, acc0[i]))));
                acc1[i] = fmaf(a.x, w0.y, fmaf(a.y, w1.y, fmaf(a.z, w2.y, fmaf(a.w, w3.y, acc1[i]))));
            }
        }
        #pragma unroll
        for (int i = 0; i < 4; i++){
            size_t o = (size_t)(m0+rg+i)*CDIM + c0;
            att[rg+i][c0]   = og1[o]  *acc0[i];
            att[rg+i][c0+1] = og1[o+1]*acc1[i];
        }
    }
    __syncthreads();
    // phase B: trans1 -> hidden; thread t -> hidden col t, 16 rows, 2 mats
    {
        float acc1[16], acc2[16];
        #pragma unroll
        for (int i = 0; i < 16; i++){ acc1[i]=0.f; acc2[i]=0.f; }
        for (int k4 = 0; k4 < CDIM/4; k4++){
            float w10 = wt1[(k4*4+0)*NHID + t], w20 = wt2[(k4*4+0)*NHID + t];
            float w11 = wt1[(k4*4+1)*NHID + t], w21 = wt2[(k4*4+1)*NHID + t];
            float w12 = wt1[(k4*4+2)*NHID + t], w22 = wt2[(k4*4+2)*NHID + t];
            float w13 = wt1[(k4*4+3)*NHID + t], w23 = wt2[(k4*4+3)*NHID + t];
            #pragma unroll
            for (int i = 0; i < 16; i++){
                float4 a = *(const float4*)&a2s[i][k4*4];
                acc1[i] = fmaf(a.x, w10, fmaf(a.y, w11, fmaf(a.z, w12, fmaf(a.w, w13, acc1[i]))));
                acc2[i] = fmaf(a.x, w20, fmaf(a.y, w21, fmaf(a.z, w22, fmaf(a.w, w23, acc2[i]))));
            }
        }
        #pragma unroll
        for (int i = 0; i < 16; i++){
            float h1 = acc1[i];
            hid[i][t] = h1*sigm(h1)*acc2[i];
        }
    }
    __syncthreads();
    // phase C: trans2 (k=256) + og2 gate + residual
    {
        int c0 = (t & 63)*2;
        int rg = (t >> 6)*4;
        float acc0[4] = {0,0,0,0}, acc1[4] = {0,0,0,0};
        for (int k4 = 0; k4 < NHID/4; k4++){
            float2 w0 = *(const float2*)&wt3[(k4*4+0)*CDIM + c0];
            float2 w1 = *(const float2*)&wt3[(k4*4+1)*CDIM + c0];
            float2 w2 = *(const float2*)&wt3[(k4*4+2)*CDIM + c0];
            float2 w3 = *(const float2*)&wt3[(k4*4+3)*CDIM + c0];
            #pragma unroll
            for (int i = 0; i < 4; i++){
                float4 a = *(const float4*)&hid[rg+i][k4*4];
                acc0[i] = fmaf(a.x, w0.x, fmaf(a.y, w1.x, fmaf(a.z, w2.x, fmaf(a.w, w3.x, acc0[i]))));
                acc1[i] = fmaf(a.x, w0.y, fmaf(a.y, w1.y, fmaf(a.z, w2.y, fmaf(a.w, w3.y, acc1[i]))));
            }
        }
        #pragma unroll
        for (int i = 0; i < 4; i++){
            size_t o = (size_t)(m0+rg+i)*CDIM + c0;
            g_a[o]   = att[rg+i][c0]   + og2[o]  *acc0[i];
            g_a[o+1] = att[rg+i][c0+1] + og2[o+1]*acc1[i];
        }
    }
}

// ---------------- host launcher ----------------
extern "C" void kernel_launch(void* const* d_in, const int* in_sizes, int n_in,
                              void* d_out, int out_size){
    const float* ql       = (const float*)d_in[0];
    const float* cl       = (const float*)d_in[1];
    const float* plm      = (const float*)d_in[2];
    const float* a2t      = (const float*)d_in[3];
    const float* tm       = (const float*)d_in[4];
    const float* ada1_gs  = (const float*)d_in[5];
    const float* ada1_ws  = (const float*)d_in[6];
    const float* ada1_bs  = (const float*)d_in[7];
    const float* ada1_wsb = (const float*)d_in[8];
    const float* wq       = (const float*)d_in[9];
    const float* bq       = (const float*)d_in[10];
    const float* wk       = (const float*)d_in[11];
    const float* wv       = (const float*)d_in[12];
    const float* gz       = (const float*)d_in[13];
    const float* bz       = (const float*)d_in[14];
    const float* wz       = (const float*)d_in[15];
    const float* wg       = (const float*)d_in[16];
    const float* wo       = (const float*)d_in[17];
    const float* wog1     = (const float*)d_in[18];
    const float* bog1     = (const float*)d_in[19];
    const float* ada2_gs  = (const float*)d_in[20];
    const float* ada2_ws  = (const float*)d_in[21];
    const float* ada2_bs  = (const float*)d_in[22];
    const float* ada2_wsb = (const float*)d_in[23];
    const float* wt1      = (const float*)d_in[24];
    const float* wt2      = (const float*)d_in[25];
    const float* wt3      = (const float*)d_in[26];
    const float* wog2     = (const float*)d_in[27];
    const float* bog2     = (const float*)d_in[28];

    float *p_lns, *p_gate1, *p_shift1, *p_gate2, *p_shift2, *p_og1, *p_og2, *p_pb;
    cudaGetSymbolAddress((void**)&p_lns,    g_lns);
    cudaGetSymbolAddress((void**)&p_gate1,  g_gate1);
    cudaGetSymbolAddress((void**)&p_shift1, g_shift1);
    cudaGetSymbolAddress((void**)&p_gate2,  g_gate2);
    cudaGetSymbolAddress((void**)&p_shift2, g_shift2);
    cudaGetSymbolAddress((void**)&p_og1,    g_og1);
    cudaGetSymbolAddress((void**)&p_og2,    g_og2);
    cudaGetSymbolAddress((void**)&p_pb,     g_pb);

    copy_in_kernel<<<NC/256, 256>>>(ql);
    ln_cl_kernel<<<NATOM/16, 128>>>(cl);
    maskbias_kernel<<<NATOM/8, 256>>>(a2t, tm);

    dim3 pg(NATOM/32, 18);
    pre_gemm_kernel<<<pg, 128>>>(p_lns, cl,
        ada1_gs, ada1_ws, ada1_bs, ada1_wsb,
        ada2_gs, ada2_ws, ada2_bs, ada2_wsb,
        wog1, bog1, wog2, bog2);

    pb_kernel<<<NATOM*NKEY/256, 256>>>(plm, gz, bz, wz);

    for (int b = 0; b < NBL; b++){
        size_t oC = (size_t)b*NC, oW = (size_t)b*CDIM*CDIM;
        dim3 qg(NATOM/32, 4);
        adaln_proj_kernel<<<qg, 128>>>(p_gate1+oC, p_shift1+oC,
                                       wq+oW, bq+(size_t)b*CDIM, wk+oW, wv+oW, wg+oW);
        dim3 ag(NQB, NHEADS);
        attn_kernel<<<ag, 128>>>(p_pb + (size_t)b*NHEADS*NATOM*NKEY);
        tail_kernel<<<NATOM/16, 256>>>(wo+oW, p_og1+oC, p_gate2+oC, p_shift2+oC,
                                       wt1+(size_t)b*CDIM*NHID, wt2+(size_t)b*CDIM*NHID,
                                       wt3+(size_t)b*NHID*CDIM, p_og2+oC);
    }
    copy_out_kernel<<<NC/256, 256>>>((float*)d_out);
}